// round 1
// baseline (speedup 1.0000x reference)
#include <cuda_runtime.h>
#include <cuda_bf16.h>

// Problem dims
#define BB 128
#define TT 128
#define VV 10000
#define EE 256
#define HH 1024
#define DD 128

// Scratch (device globals: allocation-free rule)
__device__ float g_xg[(size_t)TT * BB * 3 * HH];      // [m = t*128+b][3072], bias bi included
__device__ float g_hs[(size_t)(TT + 1) * BB * HH];    // slot s = h after s steps; slot 0 = zeros
__device__ float g_d[(size_t)TT * BB * DD];           // [m][128]
__device__ float g_logits[(size_t)TT * BB * VV];      // [m][10000]

__device__ unsigned g_bar_cnt = 0;
__device__ unsigned g_bar_phase = 0;

// ---------- packed f32x2 helpers (FFMA2: 2 fp32 MAC / instr) ----------
__device__ __forceinline__ unsigned long long pk2(float lo, float hi) {
    unsigned long long r;
    asm("mov.b64 %0, {%1, %2};" : "=l"(r) : "f"(lo), "f"(hi));
    return r;
}
__device__ __forceinline__ void upk2(float& lo, float& hi, unsigned long long v) {
    asm("mov.b64 {%0, %1}, %2;" : "=f"(lo), "=f"(hi) : "l"(v));
}
__device__ __forceinline__ void fma2(unsigned long long& acc, unsigned long long a,
                                     unsigned long long b) {
    asm("fma.rn.f32x2 %0, %1, %2, %0;" : "+l"(acc) : "l"(a), "l"(b));
}

__device__ __forceinline__ void grid_barrier(int nblk) {
    __syncthreads();
    if (threadIdx.x == 0) {
        __threadfence();
        unsigned ph = *(volatile unsigned*)&g_bar_phase;
        unsigned old = atomicAdd(&g_bar_cnt, 1);
        if (old == (unsigned)(nblk - 1)) {
            g_bar_cnt = 0;
            __threadfence();
            atomicAdd(&g_bar_phase, 1);
        } else {
            while (*(volatile unsigned*)&g_bar_phase == ph) { __nanosleep(32); }
        }
        __threadfence();
    }
    __syncthreads();
}

// =====================================================================
// Kernel 1: xg[m][0:3072] = emb[tok(m)][:] @ gru_k + gru_bi, m = t*128+b
// grid (24, 128), 256 thr.  BM=BN=128, BK=16
// =====================================================================
__global__ __launch_bounds__(256) void k_xg(const int* __restrict__ tokens,
                                            const float* __restrict__ emb,
                                            const float* __restrict__ gk,
                                            const float* __restrict__ bi) {
    __shared__ float As[16][129];   // As[k][m]
    __shared__ float Bs[16][128];   // Bs[k][n]
    __shared__ int toks[128];
    const int tid = threadIdx.x;
    const int m0 = blockIdx.y * 128, n0 = blockIdx.x * 128;
    if (tid < 128) {
        int m = m0 + tid;
        int t = m >> 7, b = m & 127;
        toks[tid] = tokens[b * TT + t];
    }
    __syncthreads();

    unsigned long long acc[8][4];
#pragma unroll
    for (int i = 0; i < 8; i++)
#pragma unroll
        for (int j = 0; j < 4; j++) acc[i][j] = 0ULL;

    const int ty = tid >> 4, tx = tid & 15;
    const int ar = tid >> 2, akq = (tid & 3) * 4;
    const int bk = tid >> 5, bn = (tid & 31) * 4;

    for (int k0 = 0; k0 < EE; k0 += 16) {
#pragma unroll
        for (int p = 0; p < 2; p++) {
            int r = p * 64 + ar;
            float4 v = *(const float4*)(emb + (size_t)toks[r] * EE + k0 + akq);
            As[akq + 0][r] = v.x; As[akq + 1][r] = v.y;
            As[akq + 2][r] = v.z; As[akq + 3][r] = v.w;
        }
#pragma unroll
        for (int p = 0; p < 2; p++) {
            int kk = p * 8 + bk;
            *(float4*)&Bs[kk][bn] =
                *(const float4*)(gk + (size_t)(k0 + kk) * (3 * HH) + n0 + bn);
        }
        __syncthreads();
#pragma unroll
        for (int kk = 0; kk < 16; kk++) {
            float a[8];
#pragma unroll
            for (int i = 0; i < 8; i++) a[i] = As[kk][ty * 8 + i];
            unsigned long long bp[4];
#pragma unroll
            for (int j = 0; j < 4; j++)
                bp[j] = *(const unsigned long long*)&Bs[kk][tx * 8 + j * 2];
#pragma unroll
            for (int i = 0; i < 8; i++) {
                unsigned long long ap = pk2(a[i], a[i]);
                fma2(acc[i][0], ap, bp[0]); fma2(acc[i][1], ap, bp[1]);
                fma2(acc[i][2], ap, bp[2]); fma2(acc[i][3], ap, bp[3]);
            }
        }
        __syncthreads();
    }
#pragma unroll
    for (int i = 0; i < 8; i++) {
        int m = m0 + ty * 8 + i;
        float* orow = g_xg + (size_t)m * (3 * HH) + n0 + tx * 8;
#pragma unroll
        for (int j = 0; j < 4; j++) {
            float lo, hi; upk2(lo, hi, acc[i][j]);
            int n = n0 + tx * 8 + j * 2;
            orow[j * 2 + 0] = lo + bi[n];
            orow[j * 2 + 1] = hi + bi[n + 1];
        }
    }
}

// =====================================================================
// Kernel 2: persistent GRU scan. 128 blocks x 256 thr, 8 units/block.
// Recurrent weights resident in SMEM for all 128 steps.
// =====================================================================
#define SCAN_NBLK 128
#define SCAN_SMEM (1024 * 24 * 4 + 32 * 129 * 4)

__global__ __launch_bounds__(256) void k_scan(const float* __restrict__ rk,
                                              const float* __restrict__ br) {
    extern __shared__ float sm[];
    float* wsm = sm;               // [1024][24]  cols: z0..z7, r0..r7, h0..h7
    float* hsm = sm + 1024 * 24;   // [32][129]   hsm[k][b]
    const int tid = threadIdx.x;
    const int u0 = blockIdx.x * 8;

    // Load this block's recurrent weight slice
    for (int idx = tid; idx < 1024 * 24; idx += 256) {
        int k = idx / 24, j = idx - k * 24;
        int g = j >> 3, u = j & 7;
        wsm[k * 24 + j] = rk[(size_t)k * (3 * HH) + g * HH + u0 + u];
    }
    // Zero h0 (slot 0)
    for (int i = tid + blockIdx.x * 256; i < BB * HH; i += SCAN_NBLK * 256)
        g_hs[i] = 0.f;
    grid_barrier(SCAN_NBLK);

    const int up = tid & 3;        // unit pair 0..3
    const int bg = tid >> 2;       // batch group 0..63 (2 b each)
    const int b0 = bg * 2;
    const int zc = up * 2;         // local even unit col

    const float brz0 = br[u0 + zc],        brz1 = br[u0 + zc + 1];
    const float brr0 = br[HH + u0 + zc],   brr1 = br[HH + u0 + zc + 1];
    const float brh0 = br[2 * HH + u0 + zc], brh1 = br[2 * HH + u0 + zc + 1];

    const int lr = tid >> 3;          // 0..31
    const int lk = (tid & 7) * 4;     // 0..28

    for (int t = 0; t < TT; t++) {
        const float* hprev = g_hs + (size_t)t * (BB * HH);
        float* hnew = g_hs + (size_t)(t + 1) * (BB * HH);
        unsigned long long acc[3][2] = {{0ULL, 0ULL}, {0ULL, 0ULL}, {0ULL, 0ULL}};

        float4 pf[4];
#pragma unroll
        for (int p = 0; p < 4; p++)
            pf[p] = *(const float4*)(hprev + (size_t)(p * 32 + lr) * HH + lk);

        for (int c = 0; c < 32; c++) {
#pragma unroll
            for (int p = 0; p < 4; p++) {
                int b = p * 32 + lr;
                hsm[(lk + 0) * 129 + b] = pf[p].x;
                hsm[(lk + 1) * 129 + b] = pf[p].y;
                hsm[(lk + 2) * 129 + b] = pf[p].z;
                hsm[(lk + 3) * 129 + b] = pf[p].w;
            }
            __syncthreads();
            if (c < 31) {
                int kbase = (c + 1) * 32;
#pragma unroll
                for (int p = 0; p < 4; p++)
                    pf[p] = *(const float4*)(hprev + (size_t)(p * 32 + lr) * HH +
                                             kbase + lk);
            }
#pragma unroll
            for (int kk = 0; kk < 32; kk++) {
                const float* wrow = wsm + (size_t)(c * 32 + kk) * 24;
                unsigned long long wzp = *(const unsigned long long*)(wrow + zc);
                unsigned long long wrp = *(const unsigned long long*)(wrow + 8 + zc);
                unsigned long long whp = *(const unsigned long long*)(wrow + 16 + zc);
                float h0v = hsm[kk * 129 + b0];
                float h1v = hsm[kk * 129 + b0 + 1];
                unsigned long long hp0 = pk2(h0v, h0v);
                unsigned long long hp1 = pk2(h1v, h1v);
                fma2(acc[0][0], hp0, wzp); fma2(acc[0][1], hp1, wzp);
                fma2(acc[1][0], hp0, wrp); fma2(acc[1][1], hp1, wrp);
                fma2(acc[2][0], hp0, whp); fma2(acc[2][1], hp1, whp);
            }
            __syncthreads();
        }

        // Gates + state update for (2 batches) x (2 units)
#pragma unroll
        for (int i = 0; i < 2; i++) {
            int b = b0 + i;
            const float* xrow = g_xg + ((size_t)t * BB + b) * (3 * HH);
            float az_lo, az_hi, ar_lo, ar_hi, ah_lo, ah_hi;
            upk2(az_lo, az_hi, acc[0][i]);
            upk2(ar_lo, ar_hi, acc[1][i]);
            upk2(ah_lo, ah_hi, acc[2][i]);
#pragma unroll
            for (int uu = 0; uu < 2; uu++) {
                int col = u0 + zc + uu;
                float rz = (uu ? az_hi : az_lo) + (uu ? brz1 : brz0);
                float rr = (uu ? ar_hi : ar_lo) + (uu ? brr1 : brr0);
                float rh = (uu ? ah_hi : ah_lo) + (uu ? brh1 : brh0);
                float xz = xrow[col];
                float xr = xrow[HH + col];
                float xh = xrow[2 * HH + col];
                float z = 1.f / (1.f + expf(-(xz + rz)));
                float r = 1.f / (1.f + expf(-(xr + rr)));
                float hh = tanhf(xh + r * rh);
                float hp = hprev[(size_t)b * HH + col];
                hnew[(size_t)b * HH + col] = z * hp + (1.f - z) * hh;
            }
        }
        grid_barrier(SCAN_NBLK);
    }
}

// =====================================================================
// Kernel 3: d = relu(hs @ w1 + b1).  M=16384, N=128, K=1024.
// grid (1, 128)
// =====================================================================
__global__ __launch_bounds__(256) void k_mlp(const float* __restrict__ w1,
                                             const float* __restrict__ b1) {
    __shared__ float As[16][129];
    __shared__ float Bs[16][128];
    const int tid = threadIdx.x;
    const int m0 = blockIdx.y * 128;
    unsigned long long acc[8][4];
#pragma unroll
    for (int i = 0; i < 8; i++)
#pragma unroll
        for (int j = 0; j < 4; j++) acc[i][j] = 0ULL;

    const int ty = tid >> 4, tx = tid & 15;
    const int ar = tid >> 2, akq = (tid & 3) * 4;
    const int bk = tid >> 5, bn = (tid & 31) * 4;

    for (int k0 = 0; k0 < HH; k0 += 16) {
#pragma unroll
        for (int p = 0; p < 2; p++) {
            int r = p * 64 + ar;
            // row m -> hs slot (t+1), batch b : offset (m + 128) rows
            float4 v = *(const float4*)(g_hs + (size_t)(m0 + r + BB) * HH + k0 + akq);
            As[akq + 0][r] = v.x; As[akq + 1][r] = v.y;
            As[akq + 2][r] = v.z; As[akq + 3][r] = v.w;
        }
#pragma unroll
        for (int p = 0; p < 2; p++) {
            int kk = p * 8 + bk;
            *(float4*)&Bs[kk][bn] = *(const float4*)(w1 + (size_t)(k0 + kk) * DD + bn);
        }
        __syncthreads();
#pragma unroll
        for (int kk = 0; kk < 16; kk++) {
            float a[8];
#pragma unroll
            for (int i = 0; i < 8; i++) a[i] = As[kk][ty * 8 + i];
            unsigned long long bp[4];
#pragma unroll
            for (int j = 0; j < 4; j++)
                bp[j] = *(const unsigned long long*)&Bs[kk][tx * 8 + j * 2];
#pragma unroll
            for (int i = 0; i < 8; i++) {
                unsigned long long ap = pk2(a[i], a[i]);
                fma2(acc[i][0], ap, bp[0]); fma2(acc[i][1], ap, bp[1]);
                fma2(acc[i][2], ap, bp[2]); fma2(acc[i][3], ap, bp[3]);
            }
        }
        __syncthreads();
    }
#pragma unroll
    for (int i = 0; i < 8; i++) {
        int m = m0 + ty * 8 + i;
        float* orow = g_d + (size_t)m * DD + tx * 8;
#pragma unroll
        for (int j = 0; j < 4; j++) {
            float lo, hi; upk2(lo, hi, acc[i][j]);
            int n = tx * 8 + j * 2;
            orow[j * 2 + 0] = fmaxf(lo + b1[n], 0.f);
            orow[j * 2 + 1] = fmaxf(hi + b1[n + 1], 0.f);
        }
    }
}

// =====================================================================
// Kernel 4: logits = d @ w2 + b2.  M=16384, N=10000, K=128.
// grid (79, 128)
// =====================================================================
__global__ __launch_bounds__(256) void k_logits(const float* __restrict__ w2,
                                                const float* __restrict__ b2) {
    __shared__ float As[16][129];
    __shared__ float Bs[16][128];
    const int tid = threadIdx.x;
    const int m0 = blockIdx.y * 128, n0 = blockIdx.x * 128;
    unsigned long long acc[8][4];
#pragma unroll
    for (int i = 0; i < 8; i++)
#pragma unroll
        for (int j = 0; j < 4; j++) acc[i][j] = 0ULL;

    const int ty = tid >> 4, tx = tid & 15;
    const int ar = tid >> 2, akq = (tid & 3) * 4;
    const int bk = tid >> 5, bn = (tid & 31) * 4;

    for (int k0 = 0; k0 < DD; k0 += 16) {
#pragma unroll
        for (int p = 0; p < 2; p++) {
            int r = p * 64 + ar;
            float4 v = *(const float4*)(g_d + (size_t)(m0 + r) * DD + k0 + akq);
            As[akq + 0][r] = v.x; As[akq + 1][r] = v.y;
            As[akq + 2][r] = v.z; As[akq + 3][r] = v.w;
        }
#pragma unroll
        for (int p = 0; p < 2; p++) {
            int kk = p * 8 + bk;
            int col = n0 + bn;
            float4 v = make_float4(0.f, 0.f, 0.f, 0.f);
            if (col < VV)
                v = *(const float4*)(w2 + (size_t)(k0 + kk) * VV + col);
            *(float4*)&Bs[kk][bn] = v;
        }
        __syncthreads();
#pragma unroll
        for (int kk = 0; kk < 16; kk++) {
            float a[8];
#pragma unroll
            for (int i = 0; i < 8; i++) a[i] = As[kk][ty * 8 + i];
            unsigned long long bp[4];
#pragma unroll
            for (int j = 0; j < 4; j++)
                bp[j] = *(const unsigned long long*)&Bs[kk][tx * 8 + j * 2];
#pragma unroll
            for (int i = 0; i < 8; i++) {
                unsigned long long ap = pk2(a[i], a[i]);
                fma2(acc[i][0], ap, bp[0]); fma2(acc[i][1], ap, bp[1]);
                fma2(acc[i][2], ap, bp[2]); fma2(acc[i][3], ap, bp[3]);
            }
        }
        __syncthreads();
    }
#pragma unroll
    for (int i = 0; i < 8; i++) {
        int m = m0 + ty * 8 + i;
        float* orow = g_logits + (size_t)m * VV;
#pragma unroll
        for (int j = 0; j < 4; j++) {
            float lo, hi; upk2(lo, hi, acc[i][j]);
            int n = n0 + tx * 8 + j * 2;
            if (n < VV) orow[n] = lo + b2[n];
            if (n + 1 < VV) orow[n + 1] = hi + b2[n + 1];
        }
    }
}

// =====================================================================
// Kernel 5: row softmax with TEMP=0.02 (x50).  grid 16384 x 256 thr.
// out layout [b][t][v]; row m = t*128+b.
// =====================================================================
__global__ __launch_bounds__(256) void k_softmax(float* __restrict__ out) {
    const int m = blockIdx.x;
    const int b = m & 127, t = m >> 7;
    const float* lr = g_logits + (size_t)m * VV;
    float* orow = out + ((size_t)(b * TT + t)) * VV;
    __shared__ float red[8];
    const int tid = threadIdx.x;
    const int lane = tid & 31, wid = tid >> 5;

    float mx = -3.4e38f;
    for (int v = tid; v < VV; v += 256) mx = fmaxf(mx, lr[v]);
#pragma unroll
    for (int o = 16; o; o >>= 1) mx = fmaxf(mx, __shfl_xor_sync(~0u, mx, o));
    if (lane == 0) red[wid] = mx;
    __syncthreads();
    if (tid == 0) {
        float v = red[0];
#pragma unroll
        for (int i = 1; i < 8; i++) v = fmaxf(v, red[i]);
        red[0] = v;
    }
    __syncthreads();
    mx = red[0];
    __syncthreads();

    float sum = 0.f;
    for (int v = tid; v < VV; v += 256) sum += expf((lr[v] - mx) * 50.f);
#pragma unroll
    for (int o = 16; o; o >>= 1) sum += __shfl_xor_sync(~0u, sum, o);
    if (lane == 0) red[wid] = sum;
    __syncthreads();
    if (tid == 0) {
        float v = red[0];
#pragma unroll
        for (int i = 1; i < 8; i++) v += red[i];
        red[0] = v;
    }
    __syncthreads();
    float inv = 1.f / red[0];

    for (int v = tid; v < VV; v += 256)
        orow[v] = expf((lr[v] - mx) * 50.f) * inv;
}

// =====================================================================
extern "C" void kernel_launch(void* const* d_in, const int* in_sizes, int n_in,
                              void* d_out, int out_size) {
    const int* tokens   = (const int*)d_in[0];
    const float* emb    = (const float*)d_in[1];
    const float* gru_k  = (const float*)d_in[2];
    const float* gru_rk = (const float*)d_in[3];
    const float* gru_bi = (const float*)d_in[4];
    const float* gru_br = (const float*)d_in[5];
    const float* w1     = (const float*)d_in[6];
    const float* b1     = (const float*)d_in[7];
    const float* w2     = (const float*)d_in[8];
    const float* b2     = (const float*)d_in[9];
    float* out = (float*)d_out;

    cudaFuncSetAttribute(k_scan, cudaFuncAttributeMaxDynamicSharedMemorySize,
                         SCAN_SMEM);

    k_xg<<<dim3(24, 128), 256>>>(tokens, emb, gru_k, gru_bi);
    k_scan<<<SCAN_NBLK, 256, SCAN_SMEM>>>(gru_rk, gru_br);
    k_mlp<<<dim3(1, 128), 256>>>(w1, b1);
    k_logits<<<dim3(79, 128), 256>>>(w2, b2);
    k_softmax<<<TT * BB, 256>>>(out);
}

// round 4
// speedup vs baseline: 1.6644x; 1.6644x over previous
#include <cuda_runtime.h>
#include <cuda_bf16.h>
#include <cstdint>

#define BB 128
#define TT 128
#define VV 10000
#define VP 10112
#define EE 256
#define HH 1024
#define DD 128

// ------------------- device scratch (no allocs) -------------------
__device__ __nv_bfloat16 g_ehi[(size_t)VV * EE], g_elo[(size_t)VV * EE];      // [tok][k]
__device__ __nv_bfloat16 g_gkhi[(size_t)3 * HH * EE], g_gklo[(size_t)3 * HH * EE]; // [n=3072][k=256]
__device__ __nv_bfloat16 g_rkhi[(size_t)3 * HH * HH], g_rklo[(size_t)3 * HH * HH]; // [row=bid*24+g*8+u][k=1024]
__device__ __nv_bfloat16 g_w1hi[(size_t)DD * HH], g_w1lo[(size_t)DD * HH];    // [n=128][k=1024]
__device__ __nv_bfloat16 g_w2hi[(size_t)VP * DD], g_w2lo[(size_t)VP * DD];    // [n][k=128]
__device__ float g_xg[(size_t)TT * BB * 3 * HH];                              // [t][b][3072]
__device__ __nv_bfloat16 g_hshi[(size_t)(TT + 1) * BB * HH];                  // [t][b][u]
__device__ __nv_bfloat16 g_hslo[(size_t)(TT + 1) * BB * HH];
__device__ __nv_bfloat16 g_dhi[(size_t)TT * BB * DD], g_dlo[(size_t)TT * BB * DD];
__device__ float g_logits[(size_t)TT * BB * VV];
__device__ unsigned g_bar_cnt = 0, g_bar_phase = 0;

// ------------------- helpers -------------------
__device__ __forceinline__ uint32_t smem_u32(const void* p) {
    uint32_t a;
    asm("{ .reg .u64 t; cvta.to.shared.u64 t, %1; cvt.u32.u64 %0, t; }"
        : "=r"(a) : "l"(p));
    return a;
}
__device__ __forceinline__ void ldsm4(uint32_t* r, uint32_t a) {
    asm volatile("ldmatrix.sync.aligned.m8n8.x4.shared.b16 {%0,%1,%2,%3}, [%4];"
                 : "=r"(r[0]), "=r"(r[1]), "=r"(r[2]), "=r"(r[3]) : "r"(a));
}
__device__ __forceinline__ void ldsm2(uint32_t* r, uint32_t a) {
    asm volatile("ldmatrix.sync.aligned.m8n8.x2.shared.b16 {%0,%1}, [%2];"
                 : "=r"(r[0]), "=r"(r[1]) : "r"(a));
}
__device__ __forceinline__ void mma16816(float* c, const uint32_t* a,
                                         uint32_t b0, uint32_t b1) {
    asm volatile(
        "mma.sync.aligned.m16n8k16.row.col.f32.bf16.bf16.f32 "
        "{%0,%1,%2,%3}, {%4,%5,%6,%7}, {%8,%9}, {%0,%1,%2,%3};"
        : "+f"(c[0]), "+f"(c[1]), "+f"(c[2]), "+f"(c[3])
        : "r"(a[0]), "r"(a[1]), "r"(a[2]), "r"(a[3]), "r"(b0), "r"(b1));
}
__device__ __forceinline__ void bsplit(float v, __nv_bfloat16& h, __nv_bfloat16& l) {
    h = __float2bfloat16(v);
    l = __float2bfloat16(v - __bfloat162float(h));
}
__device__ __forceinline__ float sigm(float x) { return 1.f / (1.f + __expf(-x)); }

__device__ __forceinline__ void grid_barrier(int nblk) {
    __syncthreads();
    if (threadIdx.x == 0) {
        __threadfence();
        unsigned ph = *(volatile unsigned*)&g_bar_phase;
        unsigned old = atomicAdd(&g_bar_cnt, 1);
        if (old == (unsigned)(nblk - 1)) {
            g_bar_cnt = 0;
            __threadfence();
            atomicAdd(&g_bar_phase, 1);
        } else {
            while (*(volatile unsigned*)&g_bar_phase == ph) { __nanosleep(32); }
        }
        __threadfence();
    }
    __syncthreads();
}

// =====================================================================
// k_split: pre-split weights into bf16 hi/lo, B-layouts
// =====================================================================
__global__ __launch_bounds__(256) void k_split(const float* __restrict__ emb,
                                               const float* __restrict__ gk,
                                               const float* __restrict__ rk,
                                               const float* __restrict__ w1,
                                               const float* __restrict__ w2) {
    const size_t stride = (size_t)gridDim.x * blockDim.x;
    const size_t t0 = (size_t)blockIdx.x * blockDim.x + threadIdx.x;
    for (size_t i = t0; i < (size_t)VV * EE; i += stride)
        bsplit(emb[i], g_ehi[i], g_elo[i]);
    for (size_t i = t0; i < (size_t)3 * HH * EE; i += stride) {
        int n = (int)(i % (3 * HH)), k = (int)(i / (3 * HH));
        bsplit(gk[(size_t)k * 3 * HH + n], g_gkhi[(size_t)n * EE + k],
               g_gklo[(size_t)n * EE + k]);
    }
    for (size_t i = t0; i < (size_t)3 * HH * HH; i += stride) {
        int c = (int)(i % (3 * HH)), k = (int)(i / (3 * HH));
        int row = ((c & 1023) >> 3) * 24 + (c >> 10) * 8 + (c & 7);
        bsplit(rk[(size_t)k * 3 * HH + c], g_rkhi[(size_t)row * HH + k],
               g_rklo[(size_t)row * HH + k]);
    }
    for (size_t i = t0; i < (size_t)DD * HH; i += stride) {
        int n = (int)(i % DD), k = (int)(i / DD);
        bsplit(w1[(size_t)k * DD + n], g_w1hi[(size_t)n * HH + k],
               g_w1lo[(size_t)n * HH + k]);
    }
    for (size_t i = t0; i < (size_t)VP * DD; i += stride) {
        int n = (int)(i % VP), k = (int)(i / VP);
        float v = (n < VV) ? w2[(size_t)k * VV + n] : 0.f;
        bsplit(v, g_w2hi[(size_t)n * DD + k], g_w2lo[(size_t)n * DD + k]);
    }
}

// =====================================================================
// k_xg: xg = emb[tok] @ gru_k + bi.  grid (24 n-tiles, 128 t), 256 thr
// =====================================================================
#define XA_P 264
#define XB_P 136
#define XG_SMEM ((2 * 128 * XA_P + 2 * 128 * XB_P) * 2)
__global__ void __launch_bounds__(256, 1)
k_xg(const int* __restrict__ tokens, const float* __restrict__ bi) {
    extern __shared__ __nv_bfloat16 xsm[];
    __nv_bfloat16* Ahi = xsm;
    __nv_bfloat16* Alo = Ahi + 128 * XA_P;
    __nv_bfloat16* Bhi = Alo + 128 * XA_P;
    __nv_bfloat16* Blo = Bhi + 128 * XB_P;
    __shared__ float sb[128];
    const int tid = threadIdx.x, wid = tid >> 5, lane = tid & 31;
    const int t = blockIdx.y, n0 = blockIdx.x * 128;
    if (tid < 128) sb[tid] = bi[n0 + tid];
    {   // gather A (emb rows, split)
        const int r = tid >> 1, half = tid & 1;
        const int tok = tokens[r * TT + t];
        const __nv_bfloat16* sh = g_ehi + (size_t)tok * EE + half * 128;
        const __nv_bfloat16* sl = g_elo + (size_t)tok * EE + half * 128;
        __nv_bfloat16* dh = Ahi + r * XA_P + half * 128;
        __nv_bfloat16* dl = Alo + r * XA_P + half * 128;
#pragma unroll
        for (int j = 0; j < 128; j += 8) {
            *(uint4*)(dh + j) = *(const uint4*)(sh + j);
            *(uint4*)(dl + j) = *(const uint4*)(sl + j);
        }
    }
    float acc[16][4];
#pragma unroll
    for (int i = 0; i < 16; i++)
#pragma unroll
        for (int j = 0; j < 4; j++) acc[i][j] = 0.f;

    const int arow = wid * 16 + (lane & 15);
    const int ahalf = lane >> 4;
    const uint32_t aHi = smem_u32(Ahi + arow * XA_P + ahalf * 8);
    const uint32_t aLo = smem_u32(Alo + arow * XA_P + ahalf * 8);
    const int br15 = lane & 15, bh8 = lane >> 4;

    for (int kc = 0; kc < 2; kc++) {
        __syncthreads();
        {
            const int n = tid >> 1, half = tid & 1;
            const __nv_bfloat16* sh = g_gkhi + (size_t)(n0 + n) * EE + kc * 128 + half * 64;
            const __nv_bfloat16* sl = g_gklo + (size_t)(n0 + n) * EE + kc * 128 + half * 64;
            __nv_bfloat16* dh = Bhi + n * XB_P + half * 64;
            __nv_bfloat16* dl = Blo + n * XB_P + half * 64;
#pragma unroll
            for (int j = 0; j < 64; j += 8) {
                *(uint4*)(dh + j) = *(const uint4*)(sh + j);
                *(uint4*)(dl + j) = *(const uint4*)(sl + j);
            }
        }
        __syncthreads();
#pragma unroll
        for (int kk = 0; kk < 8; kk++) {
            uint32_t ah[4], al[4];
            ldsm4(ah, aHi + (kc * 128 + kk * 16) * 2);
            ldsm4(al, aLo + (kc * 128 + kk * 16) * 2);
#pragma unroll
            for (int p = 0; p < 8; p++) {
                uint32_t bh[4], bl[4];
                ldsm4(bh, smem_u32(Bhi + (p * 16 + br15) * XB_P + kk * 16 + bh8 * 8));
                ldsm4(bl, smem_u32(Blo + (p * 16 + br15) * XB_P + kk * 16 + bh8 * 8));
                mma16816(acc[2 * p], ah, bh[0], bh[2]);
                mma16816(acc[2 * p], ah, bl[0], bl[2]);
                mma16816(acc[2 * p], al, bh[0], bh[2]);
                mma16816(acc[2 * p + 1], ah, bh[1], bh[3]);
                mma16816(acc[2 * p + 1], ah, bl[1], bl[3]);
                mma16816(acc[2 * p + 1], al, bh[1], bh[3]);
            }
        }
    }
    const int rr = wid * 16 + (lane >> 2), cc = 2 * (lane & 3);
    float* outb = g_xg + (size_t)t * BB * 3072 + n0;
#pragma unroll
    for (int p = 0; p < 16; p++) {
        int col = p * 8 + cc;
        float2 v0 = {acc[p][0] + sb[col], acc[p][1] + sb[col + 1]};
        float2 v1 = {acc[p][2] + sb[col], acc[p][3] + sb[col + 1]};
        *(float2*)(outb + (size_t)rr * 3072 + col) = v0;
        *(float2*)(outb + (size_t)(rr + 8) * 3072 + col) = v1;
    }
}

// =====================================================================
// k_scan: persistent GRU scan on mma.sync. 128 blocks x 256 thr.
// Block owns units u0..u0+7 (24 gate cols), weights resident in SMEM.
// =====================================================================
#define SC_NB 128
#define SC_WP 1032
#define SC_AP 72
#define SCAN_SMEM ((2 * 24 * SC_WP + 2 * 2 * 128 * SC_AP) * 2)
__global__ void __launch_bounds__(256, 1) k_scan(const float* __restrict__ br) {
    extern __shared__ __nv_bfloat16 ssm[];
    __nv_bfloat16* Whi = ssm;                     // [24][1032]
    __nv_bfloat16* Wlo = Whi + 24 * SC_WP;
    __nv_bfloat16* Abuf = Wlo + 24 * SC_WP;       // 2 x (hi[128*72], lo[128*72])
    const int tid = threadIdx.x, wid = tid >> 5, lane = tid & 31;
    const int bid = blockIdx.x, u0 = bid * 8;

    for (int i = tid; i < 24 * 128; i += 256) {   // resident weights
        int n = i >> 7, j = (i & 127) * 8;
        *(uint4*)(Whi + n * SC_WP + j) = *(const uint4*)(g_rkhi + ((size_t)(bid * 24 + n)) * HH + j);
        *(uint4*)(Wlo + n * SC_WP + j) = *(const uint4*)(g_rklo + ((size_t)(bid * 24 + n)) * HH + j);
    }
    for (int i = tid; i < 128; i += 256) {        // zero h slot0, batch row = bid
        uint4 z = {0, 0, 0, 0};
        *(uint4*)(g_hshi + (size_t)bid * HH + i * 8) = z;
        *(uint4*)(g_hslo + (size_t)bid * HH + i * 8) = z;
    }
    const int cc = 2 * (lane & 3);
    const float bz0 = br[u0 + cc], bz1 = br[u0 + cc + 1];
    const float brr0 = br[HH + u0 + cc], brr1 = br[HH + u0 + cc + 1];
    const float bh0 = br[2 * HH + u0 + cc], bh1 = br[2 * HH + u0 + cc + 1];
    float hp[4] = {0.f, 0.f, 0.f, 0.f};
    const int r1 = wid * 16 + (lane >> 2);
    const int arow = wid * 16 + (lane & 15), ahalf = lane >> 4;
    const int b15 = lane & 15, bh8 = lane >> 4;
    const int b7 = lane & 7, bq = (lane >> 3) & 1;
    const int lr = tid >> 1, lp = tid & 1;
    grid_barrier(SC_NB);

    for (int t = 0; t < TT; t++) {
        // prefetch x-side gate activations for this thread's 4 (row,unit) outputs
        const float* xb = g_xg + (size_t)t * BB * 3072;
        float2 xz1 = *(const float2*)(xb + (size_t)r1 * 3072 + u0 + cc);
        float2 xr1 = *(const float2*)(xb + (size_t)r1 * 3072 + HH + u0 + cc);
        float2 xh1 = *(const float2*)(xb + (size_t)r1 * 3072 + 2 * HH + u0 + cc);
        float2 xz2 = *(const float2*)(xb + (size_t)(r1 + 8) * 3072 + u0 + cc);
        float2 xr2 = *(const float2*)(xb + (size_t)(r1 + 8) * 3072 + HH + u0 + cc);
        float2 xh2 = *(const float2*)(xb + (size_t)(r1 + 8) * 3072 + 2 * HH + u0 + cc);

        const __nv_bfloat16* Hhi = g_hshi + (size_t)t * BB * HH;
        const __nv_bfloat16* Hlo = g_hslo + (size_t)t * BB * HH;
        float acc[3][4];
#pragma unroll
        for (int i = 0; i < 3; i++)
#pragma unroll
            for (int j = 0; j < 4; j++) acc[i][j] = 0.f;

        {   // load chunk 0
            __nv_bfloat16* Ch = Abuf;
            __nv_bfloat16* Cl = Abuf + 128 * SC_AP;
#pragma unroll
            for (int j = 0; j < 4; j++) {
                *(uint4*)(Ch + lr * SC_AP + lp * 32 + j * 8) =
                    *(const uint4*)(Hhi + (size_t)lr * HH + lp * 32 + j * 8);
                *(uint4*)(Cl + lr * SC_AP + lp * 32 + j * 8) =
                    *(const uint4*)(Hlo + (size_t)lr * HH + lp * 32 + j * 8);
            }
        }
        __syncthreads();
        for (int c = 0; c < 16; c++) {
            __nv_bfloat16* Ch = Abuf + (c & 1) * (2 * 128 * SC_AP);
            __nv_bfloat16* Cl = Ch + 128 * SC_AP;
            uint4 pre[8];
            if (c < 15) {
                const __nv_bfloat16* sh = Hhi + (size_t)lr * HH + (c + 1) * 64 + lp * 32;
                const __nv_bfloat16* sl = Hlo + (size_t)lr * HH + (c + 1) * 64 + lp * 32;
#pragma unroll
                for (int j = 0; j < 4; j++) {
                    pre[j] = *(const uint4*)(sh + j * 8);
                    pre[4 + j] = *(const uint4*)(sl + j * 8);
                }
            }
            const uint32_t aHi = smem_u32(Ch + arow * SC_AP + ahalf * 8);
            const uint32_t aLo = smem_u32(Cl + arow * SC_AP + ahalf * 8);
#pragma unroll
            for (int kk = 0; kk < 4; kk++) {
                uint32_t ah[4], al[4];
                ldsm4(ah, aHi + kk * 32);
                ldsm4(al, aLo + kk * 32);
                const int kcol = c * 64 + kk * 16;
                uint32_t wh[4], wl[4], w2h[2], w2l[2];
                ldsm4(wh, smem_u32(Whi + b15 * SC_WP + kcol + bh8 * 8));
                ldsm4(wl, smem_u32(Wlo + b15 * SC_WP + kcol + bh8 * 8));
                ldsm2(w2h, smem_u32(Whi + (16 + b7) * SC_WP + kcol + bq * 8));
                ldsm2(w2l, smem_u32(Wlo + (16 + b7) * SC_WP + kcol + bq * 8));
                mma16816(acc[0], ah, wh[0], wh[2]);
                mma16816(acc[0], ah, wl[0], wl[2]);
                mma16816(acc[0], al, wh[0], wh[2]);
                mma16816(acc[1], ah, wh[1], wh[3]);
                mma16816(acc[1], ah, wl[1], wl[3]);
                mma16816(acc[1], al, wh[1], wh[3]);
                mma16816(acc[2], ah, w2h[0], w2h[1]);
                mma16816(acc[2], ah, w2l[0], w2l[1]);
                mma16816(acc[2], al, w2h[0], w2h[1]);
            }
            if (c < 15) {
                __nv_bfloat16* Nh = Abuf + ((c + 1) & 1) * (2 * 128 * SC_AP);
                __nv_bfloat16* Nl = Nh + 128 * SC_AP;
#pragma unroll
                for (int j = 0; j < 4; j++) {
                    *(uint4*)(Nh + lr * SC_AP + lp * 32 + j * 8) = pre[j];
                    *(uint4*)(Nl + lr * SC_AP + lp * 32 + j * 8) = pre[4 + j];
                }
            }
            __syncthreads();
        }
        // gates + state update (rows r1, r1+8; units u0+cc, +1)
        {
            float z, r, hh;
            z = sigm(xz1.x + acc[0][0] + bz0);
            r = sigm(xr1.x + acc[1][0] + brr0);
            hh = tanhf(xh1.x + r * (acc[2][0] + bh0));
            hp[0] = z * hp[0] + (1.f - z) * hh;
            z = sigm(xz1.y + acc[0][1] + bz1);
            r = sigm(xr1.y + acc[1][1] + brr1);
            hh = tanhf(xh1.y + r * (acc[2][1] + bh1));
            hp[1] = z * hp[1] + (1.f - z) * hh;
            z = sigm(xz2.x + acc[0][2] + bz0);
            r = sigm(xr2.x + acc[1][2] + brr0);
            hh = tanhf(xh2.x + r * (acc[2][2] + bh0));
            hp[2] = z * hp[2] + (1.f - z) * hh;
            z = sigm(xz2.y + acc[0][3] + bz1);
            r = sigm(xr2.y + acc[1][3] + brr1);
            hh = tanhf(xh2.y + r * (acc[2][3] + bh1));
            hp[3] = z * hp[3] + (1.f - z) * hh;

            __nv_bfloat16 h0, l0, h1, l1;
            bsplit(hp[0], h0, l0); bsplit(hp[1], h1, l1);
            size_t o1 = ((size_t)(t + 1) * BB + r1) * HH + u0 + cc;
            *(__nv_bfloat162*)(g_hshi + o1) = __nv_bfloat162(h0, h1);
            *(__nv_bfloat162*)(g_hslo + o1) = __nv_bfloat162(l0, l1);
            bsplit(hp[2], h0, l0); bsplit(hp[3], h1, l1);
            size_t o2 = ((size_t)(t + 1) * BB + r1 + 8) * HH + u0 + cc;
            *(__nv_bfloat162*)(g_hshi + o2) = __nv_bfloat162(h0, h1);
            *(__nv_bfloat162*)(g_hslo + o2) = __nv_bfloat162(l0, l1);
        }
        __threadfence();
        grid_barrier(SC_NB);
    }
}

// =====================================================================
// k_mlp: d = relu(hs @ w1 + b1), split output. grid 128 (=t), 256 thr
// =====================================================================
#define MB_P 136
#define MLP_SMEM (4 * 128 * MB_P * 2)
__global__ void __launch_bounds__(256, 1) k_mlp(const float* __restrict__ b1) {
    extern __shared__ __nv_bfloat16 msm[];
    __nv_bfloat16* Ahi = msm;
    __nv_bfloat16* Alo = Ahi + 128 * MB_P;
    __nv_bfloat16* Bhi = Alo + 128 * MB_P;
    __nv_bfloat16* Blo = Bhi + 128 * MB_P;
    __shared__ float sb[128];
    const int tid = threadIdx.x, wid = tid >> 5, lane = tid & 31;
    const int t = blockIdx.x;
    if (tid < 128) sb[tid] = b1[tid];
    float acc[16][4];
#pragma unroll
    for (int i = 0; i < 16; i++)
#pragma unroll
        for (int j = 0; j < 4; j++) acc[i][j] = 0.f;
    const int arow = wid * 16 + (lane & 15), ahalf = lane >> 4;
    const int br15 = lane & 15, bh8 = lane >> 4;
    const int lr = tid >> 1, lp = tid & 1;

    for (int kc = 0; kc < 8; kc++) {
        __syncthreads();
        {
            const __nv_bfloat16* sh = g_hshi + ((size_t)(t + 1) * BB + lr) * HH + kc * 128 + lp * 64;
            const __nv_bfloat16* sl = g_hslo + ((size_t)(t + 1) * BB + lr) * HH + kc * 128 + lp * 64;
            const __nv_bfloat16* wh = g_w1hi + (size_t)lr * HH + kc * 128 + lp * 64;
            const __nv_bfloat16* wl = g_w1lo + (size_t)lr * HH + kc * 128 + lp * 64;
#pragma unroll
            for (int j = 0; j < 64; j += 8) {
                *(uint4*)(Ahi + lr * MB_P + lp * 64 + j) = *(const uint4*)(sh + j);
                *(uint4*)(Alo + lr * MB_P + lp * 64 + j) = *(const uint4*)(sl + j);
                *(uint4*)(Bhi + lr * MB_P + lp * 64 + j) = *(const uint4*)(wh + j);
                *(uint4*)(Blo + lr * MB_P + lp * 64 + j) = *(const uint4*)(wl + j);
            }
        }
        __syncthreads();
#pragma unroll
        for (int kk = 0; kk < 8; kk++) {
            uint32_t ah[4], al[4];
            ldsm4(ah, smem_u32(Ahi + arow * MB_P + ahalf * 8 + kk * 16));
            ldsm4(al, smem_u32(Alo + arow * MB_P + ahalf * 8 + kk * 16));
#pragma unroll
            for (int p = 0; p < 8; p++) {
                uint32_t bh[4], bl[4];
                ldsm4(bh, smem_u32(Bhi + (p * 16 + br15) * MB_P + kk * 16 + bh8 * 8));
                ldsm4(bl, smem_u32(Blo + (p * 16 + br15) * MB_P + kk * 16 + bh8 * 8));
                mma16816(acc[2 * p], ah, bh[0], bh[2]);
                mma16816(acc[2 * p], ah, bl[0], bl[2]);
                mma16816(acc[2 * p], al, bh[0], bh[2]);
                mma16816(acc[2 * p + 1], ah, bh[1], bh[3]);
                mma16816(acc[2 * p + 1], ah, bl[1], bl[3]);
                mma16816(acc[2 * p + 1], al, bh[1], bh[3]);
            }
        }
    }
    const int rr = wid * 16 + (lane >> 2), cc = 2 * (lane & 3);
    const int m1 = t * BB + rr, m2 = m1 + 8;
#pragma unroll
    for (int p = 0; p < 16; p++) {
        int col = p * 8 + cc;
        float d0 = fmaxf(acc[p][0] + sb[col], 0.f);
        float d1 = fmaxf(acc[p][1] + sb[col + 1], 0.f);
        float d2 = fmaxf(acc[p][2] + sb[col], 0.f);
        float d3 = fmaxf(acc[p][3] + sb[col + 1], 0.f);
        __nv_bfloat16 h0, l0, h1, l1;
        bsplit(d0, h0, l0); bsplit(d1, h1, l1);
        *(__nv_bfloat162*)(g_dhi + (size_t)m1 * DD + col) = __nv_bfloat162(h0, h1);
        *(__nv_bfloat162*)(g_dlo + (size_t)m1 * DD + col) = __nv_bfloat162(l0, l1);
        bsplit(d2, h0, l0); bsplit(d3, h1, l1);
        *(__nv_bfloat162*)(g_dhi + (size_t)m2 * DD + col) = __nv_bfloat162(h0, h1);
        *(__nv_bfloat162*)(g_dlo + (size_t)m2 * DD + col) = __nv_bfloat162(l0, l1);
    }
}

// =====================================================================
// k_logits: logits = d @ w2 + b2. grid (79 n, 128 m), 256 thr
// =====================================================================
#define LG_SMEM (4 * 128 * MB_P * 2)
__global__ void __launch_bounds__(256, 1) k_logits(const float* __restrict__ b2) {
    extern __shared__ __nv_bfloat16 lsm[];
    __nv_bfloat16* Ahi = lsm;
    __nv_bfloat16* Alo = Ahi + 128 * MB_P;
    __nv_bfloat16* Bhi = Alo + 128 * MB_P;
    __nv_bfloat16* Blo = Bhi + 128 * MB_P;
    __shared__ float sb[128];
    const int tid = threadIdx.x, wid = tid >> 5, lane = tid & 31;
    const int m0 = blockIdx.y * 128, n0 = blockIdx.x * 128;
    if (tid < 128) sb[tid] = (n0 + tid < VV) ? b2[n0 + tid] : 0.f;
    {
        const int lr = tid >> 1, lp = tid & 1;
        const __nv_bfloat16* sh = g_dhi + (size_t)(m0 + lr) * DD + lp * 64;
        const __nv_bfloat16* sl = g_dlo + (size_t)(m0 + lr) * DD + lp * 64;
        const __nv_bfloat16* wh = g_w2hi + (size_t)(n0 + lr) * DD + lp * 64;
        const __nv_bfloat16* wl = g_w2lo + (size_t)(n0 + lr) * DD + lp * 64;
#pragma unroll
        for (int j = 0; j < 64; j += 8) {
            *(uint4*)(Ahi + lr * MB_P + lp * 64 + j) = *(const uint4*)(sh + j);
            *(uint4*)(Alo + lr * MB_P + lp * 64 + j) = *(const uint4*)(sl + j);
            *(uint4*)(Bhi + lr * MB_P + lp * 64 + j) = *(const uint4*)(wh + j);
            *(uint4*)(Blo + lr * MB_P + lp * 64 + j) = *(const uint4*)(wl + j);
        }
    }
    __syncthreads();
    float acc[16][4];
#pragma unroll
    for (int i = 0; i < 16; i++)
#pragma unroll
        for (int j = 0; j < 4; j++) acc[i][j] = 0.f;
    const int arow = wid * 16 + (lane & 15), ahalf = lane >> 4;
    const int br15 = lane & 15, bh8 = lane >> 4;
#pragma unroll
    for (int kk = 0; kk < 8; kk++) {
        uint32_t ah[4], al[4];
        ldsm4(ah, smem_u32(Ahi + arow * MB_P + ahalf * 8 + kk * 16));
        ldsm4(al, smem_u32(Alo + arow * MB_P + ahalf * 8 + kk * 16));
#pragma unroll
        for (int p = 0; p < 8; p++) {
            uint32_t bh[4], bl[4];
            ldsm4(bh, smem_u32(Bhi + (p * 16 + br15) * MB_P + kk * 16 + bh8 * 8));
            ldsm4(bl, smem_u32(Blo + (p * 16 + br15) * MB_P + kk * 16 + bh8 * 8));
            mma16816(acc[2 * p], ah, bh[0], bh[2]);
            mma16816(acc[2 * p], ah, bl[0], bl[2]);
            mma16816(acc[2 * p], al, bh[0], bh[2]);
            mma16816(acc[2 * p + 1], ah, bh[1], bh[3]);
            mma16816(acc[2 * p + 1], ah, bl[1], bl[3]);
            mma16816(acc[2 * p + 1], al, bh[1], bh[3]);
        }
    }
    const int rr = wid * 16 + (lane >> 2), cc = 2 * (lane & 3);
    float* o1 = g_logits + (size_t)(m0 + rr) * VV;
    float* o2 = g_logits + (size_t)(m0 + rr + 8) * VV;
#pragma unroll
    for (int p = 0; p < 16; p++) {
        int col = n0 + p * 8 + cc;
        if (col < VV) {
            float2 v0 = {acc[p][0] + sb[p * 8 + cc], acc[p][1] + sb[p * 8 + cc + 1]};
            float2 v1 = {acc[p][2] + sb[p * 8 + cc], acc[p][3] + sb[p * 8 + cc + 1]};
            *(float2*)(o1 + col) = v0;
            *(float2*)(o2 + col) = v1;
        }
    }
}

// =====================================================================
// k_softmax: online max+sum pass, then normalize-write. TEMP=0.02
// =====================================================================
__global__ __launch_bounds__(256) void k_softmax(float* __restrict__ out) {
    const int m = blockIdx.x;
    const int b = m & 127, t = m >> 7;
    const float* lr = g_logits + (size_t)m * VV;
    float* orow = out + ((size_t)b * TT + t) * VV;
    __shared__ float rm[8], rs[8];
    const int tid = threadIdx.x, lane = tid & 31, wid = tid >> 5;
    float mx = -1e30f, s = 0.f;
    for (int v = tid; v < VV; v += 256) {
        float x = lr[v] * 50.f;
        float nm = fmaxf(mx, x);
        s = s * __expf(mx - nm) + __expf(x - nm);
        mx = nm;
    }
#pragma unroll
    for (int o = 16; o; o >>= 1) {
        float om = __shfl_xor_sync(~0u, mx, o);
        float os = __shfl_xor_sync(~0u, s, o);
        float nm = fmaxf(mx, om);
        s = s * __expf(mx - nm) + os * __expf(om - nm);
        mx = nm;
    }
    if (lane == 0) { rm[wid] = mx; rs[wid] = s; }
    __syncthreads();
    if (tid == 0) {
        float M = rm[0], S = rs[0];
#pragma unroll
        for (int i = 1; i < 8; i++) {
            float nm = fmaxf(M, rm[i]);
            S = S * __expf(M - nm) + rs[i] * __expf(rm[i] - nm);
            M = nm;
        }
        rm[0] = M; rs[0] = 1.f / S;
    }
    __syncthreads();
    mx = rm[0];
    float inv = rs[0];
    for (int v = tid; v < VV; v += 256)
        orow[v] = __expf(lr[v] * 50.f - mx) * inv;
}

// =====================================================================
extern "C" void kernel_launch(void* const* d_in, const int* in_sizes, int n_in,
                              void* d_out, int out_size) {
    const int* tokens   = (const int*)d_in[0];
    const float* emb    = (const float*)d_in[1];
    const float* gru_k  = (const float*)d_in[2];
    const float* gru_rk = (const float*)d_in[3];
    const float* gru_bi = (const float*)d_in[4];
    const float* gru_br = (const float*)d_in[5];
    const float* w1     = (const float*)d_in[6];
    const float* b1     = (const float*)d_in[7];
    const float* w2     = (const float*)d_in[8];
    const float* b2     = (const float*)d_in[9];
    float* out = (float*)d_out;

    cudaFuncSetAttribute(k_xg, cudaFuncAttributeMaxDynamicSharedMemorySize, XG_SMEM);
    cudaFuncSetAttribute(k_scan, cudaFuncAttributeMaxDynamicSharedMemorySize, SCAN_SMEM);
    cudaFuncSetAttribute(k_mlp, cudaFuncAttributeMaxDynamicSharedMemorySize, MLP_SMEM);
    cudaFuncSetAttribute(k_logits, cudaFuncAttributeMaxDynamicSharedMemorySize, LG_SMEM);

    k_split<<<2048, 256>>>(emb, gru_k, gru_rk, w1, w2);
    k_xg<<<dim3(24, 128), 256, XG_SMEM>>>(tokens, gru_bi);
    k_scan<<<SC_NB, 256, SCAN_SMEM>>>(gru_br);
    k_mlp<<<128, 256, MLP_SMEM>>>(b1);
    k_logits<<<dim3(79, 128), 256, LG_SMEM>>>(b2);
    k_softmax<<<TT * BB, 256>>>(out);
}

// round 5
// speedup vs baseline: 1.9577x; 1.1762x over previous
#include <cuda_runtime.h>
#include <cuda_bf16.h>
#include <cstdint>

#define BB 128
#define TT 128
#define VV 10000
#define VP 10112
#define EE 256
#define HH 1024
#define DD 128

// ------------------- device scratch (no allocs) -------------------
__device__ __nv_bfloat16 g_ehi[(size_t)VV * EE], g_elo[(size_t)VV * EE];      // [tok][k]
__device__ __nv_bfloat16 g_gkhi[(size_t)3 * HH * EE], g_gklo[(size_t)3 * HH * EE]; // [n][k]
__device__ __nv_bfloat16 g_rkhi[(size_t)3 * HH * HH], g_rklo[(size_t)3 * HH * HH]; // [row][k]
__device__ __nv_bfloat16 g_w1hi[(size_t)DD * HH], g_w1lo[(size_t)DD * HH];    // [n][k]
__device__ __nv_bfloat16 g_w2hi[(size_t)VP * DD], g_w2lo[(size_t)VP * DD];    // [n][k]
__device__ float g_xg[(size_t)TT * BB * 3 * HH];                              // [t][b][3072]
__device__ __nv_bfloat16 g_hshi[(size_t)(TT + 1) * BB * HH];
__device__ __nv_bfloat16 g_hslo[(size_t)(TT + 1) * BB * HH];
__device__ __nv_bfloat16 g_dhi[(size_t)TT * BB * DD], g_dlo[(size_t)TT * BB * DD];
__device__ float g_logits[(size_t)TT * BB * VV];
__device__ unsigned g_bar_cnt = 0, g_bar_phase = 0;

// ------------------- helpers -------------------
__device__ __forceinline__ uint32_t smem_u32(const void* p) {
    uint32_t a;
    asm("{ .reg .u64 t; cvta.to.shared.u64 t, %1; cvt.u32.u64 %0, t; }"
        : "=r"(a) : "l"(p));
    return a;
}
__device__ __forceinline__ void ldsm4(uint32_t* r, uint32_t a) {
    asm volatile("ldmatrix.sync.aligned.m8n8.x4.shared.b16 {%0,%1,%2,%3}, [%4];"
                 : "=r"(r[0]), "=r"(r[1]), "=r"(r[2]), "=r"(r[3]) : "r"(a));
}
__device__ __forceinline__ void ldsm2(uint32_t* r, uint32_t a) {
    asm volatile("ldmatrix.sync.aligned.m8n8.x2.shared.b16 {%0,%1}, [%2];"
                 : "=r"(r[0]), "=r"(r[1]) : "r"(a));
}
__device__ __forceinline__ void mma16816(float* c, const uint32_t* a,
                                         uint32_t b0, uint32_t b1) {
    asm volatile(
        "mma.sync.aligned.m16n8k16.row.col.f32.bf16.bf16.f32 "
        "{%0,%1,%2,%3}, {%4,%5,%6,%7}, {%8,%9}, {%0,%1,%2,%3};"
        : "+f"(c[0]), "+f"(c[1]), "+f"(c[2]), "+f"(c[3])
        : "r"(a[0]), "r"(a[1]), "r"(a[2]), "r"(a[3]), "r"(b0), "r"(b1));
}
__device__ __forceinline__ void bsplit(float v, __nv_bfloat16& h, __nv_bfloat16& l) {
    h = __float2bfloat16(v);
    l = __float2bfloat16(v - __bfloat162float(h));
}
__device__ __forceinline__ float sigm(float x) { return 1.f / (1.f + __expf(-x)); }

__device__ __forceinline__ void grid_barrier(int nblk) {
    __syncthreads();
    if (threadIdx.x == 0) {
        __threadfence();
        unsigned ph = *(volatile unsigned*)&g_bar_phase;
        unsigned old = atomicAdd(&g_bar_cnt, 1);
        if (old == (unsigned)(nblk - 1)) {
            g_bar_cnt = 0;
            __threadfence();
            atomicAdd(&g_bar_phase, 1);
        } else {
            while (*(volatile unsigned*)&g_bar_phase == ph) { __nanosleep(32); }
        }
        __threadfence();
    }
    __syncthreads();
}

// =====================================================================
// k_split: pre-split weights into bf16 hi/lo, B-layouts
// =====================================================================
__global__ __launch_bounds__(256) void k_split(const float* __restrict__ emb,
                                               const float* __restrict__ gk,
                                               const float* __restrict__ rk,
                                               const float* __restrict__ w1,
                                               const float* __restrict__ w2) {
    const size_t stride = (size_t)gridDim.x * blockDim.x;
    const size_t t0 = (size_t)blockIdx.x * blockDim.x + threadIdx.x;
    for (size_t i = t0; i < (size_t)VV * EE; i += stride)
        bsplit(emb[i], g_ehi[i], g_elo[i]);
    for (size_t i = t0; i < (size_t)3 * HH * EE; i += stride) {
        int n = (int)(i % (3 * HH)), k = (int)(i / (3 * HH));
        bsplit(gk[(size_t)k * 3 * HH + n], g_gkhi[(size_t)n * EE + k],
               g_gklo[(size_t)n * EE + k]);
    }
    for (size_t i = t0; i < (size_t)3 * HH * HH; i += stride) {
        int c = (int)(i % (3 * HH)), k = (int)(i / (3 * HH));
        int row = ((c & 1023) >> 3) * 24 + (c >> 10) * 8 + (c & 7);
        bsplit(rk[(size_t)k * 3 * HH + c], g_rkhi[(size_t)row * HH + k],
               g_rklo[(size_t)row * HH + k]);
    }
    for (size_t i = t0; i < (size_t)DD * HH; i += stride) {
        int n = (int)(i % DD), k = (int)(i / DD);
        bsplit(w1[(size_t)k * DD + n], g_w1hi[(size_t)n * HH + k],
               g_w1lo[(size_t)n * HH + k]);
    }
    for (size_t i = t0; i < (size_t)VP * DD; i += stride) {
        int n = (int)(i % VP), k = (int)(i / VP);
        float v = (n < VV) ? w2[(size_t)k * VV + n] : 0.f;
        bsplit(v, g_w2hi[(size_t)n * DD + k], g_w2lo[(size_t)n * DD + k]);
    }
}

// =====================================================================
// k_xg: xg = emb[tok] @ gru_k + bi.  grid (24 n-tiles, 128 t), 256 thr
// B staged in smem per 128-k chunk; A fragments direct LDG (occ 2).
// =====================================================================
#define BP 136
#define XG_SMEM (2 * 128 * BP * 2)
__global__ void __launch_bounds__(256, 2)
k_xg(const int* __restrict__ tokens, const float* __restrict__ bi) {
    extern __shared__ __nv_bfloat16 xsm[];
    __nv_bfloat16* Bhi = xsm;
    __nv_bfloat16* Blo = Bhi + 128 * BP;
    __shared__ float sb[128];
    __shared__ int toks[128];
    const int tid = threadIdx.x, wid = tid >> 5, lane = tid & 31;
    const int t = blockIdx.y, n0 = blockIdx.x * 128;
    if (tid < 128) {
        sb[tid] = bi[n0 + tid];
        toks[tid] = tokens[tid * TT + t];
    }
    __syncthreads();
    const int r0 = wid * 16 + (lane >> 2);
    const int kq = (lane & 3) * 2;
    const __nv_bfloat16* eh0 = g_ehi + (size_t)toks[r0] * EE;
    const __nv_bfloat16* eh1 = g_ehi + (size_t)toks[r0 + 8] * EE;
    const __nv_bfloat16* el0 = g_elo + (size_t)toks[r0] * EE;
    const __nv_bfloat16* el1 = g_elo + (size_t)toks[r0 + 8] * EE;

    float acc[16][4];
#pragma unroll
    for (int i = 0; i < 16; i++)
#pragma unroll
        for (int j = 0; j < 4; j++) acc[i][j] = 0.f;
    const int br15 = lane & 15, bh8 = lane >> 4;
    const int lr = tid >> 1, lp = tid & 1;

    for (int kc = 0; kc < 2; kc++) {
        if (kc) __syncthreads();
        {
            const __nv_bfloat16* sh = g_gkhi + (size_t)(n0 + lr) * EE + kc * 128 + lp * 64;
            const __nv_bfloat16* sl = g_gklo + (size_t)(n0 + lr) * EE + kc * 128 + lp * 64;
#pragma unroll
            for (int j = 0; j < 64; j += 8) {
                *(uint4*)(Bhi + lr * BP + lp * 64 + j) = *(const uint4*)(sh + j);
                *(uint4*)(Blo + lr * BP + lp * 64 + j) = *(const uint4*)(sl + j);
            }
        }
        __syncthreads();
#pragma unroll
        for (int kt = 0; kt < 8; kt++) {
            const int k0 = kc * 128 + kt * 16 + kq;
            uint32_t ah[4], al[4];
            ah[0] = *(const uint32_t*)(eh0 + k0);
            ah[1] = *(const uint32_t*)(eh1 + k0);
            ah[2] = *(const uint32_t*)(eh0 + k0 + 8);
            ah[3] = *(const uint32_t*)(eh1 + k0 + 8);
            al[0] = *(const uint32_t*)(el0 + k0);
            al[1] = *(const uint32_t*)(el1 + k0);
            al[2] = *(const uint32_t*)(el0 + k0 + 8);
            al[3] = *(const uint32_t*)(el1 + k0 + 8);
#pragma unroll
            for (int p = 0; p < 8; p++) {
                uint32_t bh[4], bl[4];
                ldsm4(bh, smem_u32(Bhi + (p * 16 + br15) * BP + kt * 16 + bh8 * 8));
                ldsm4(bl, smem_u32(Blo + (p * 16 + br15) * BP + kt * 16 + bh8 * 8));
                mma16816(acc[2 * p], ah, bh[0], bh[2]);
                mma16816(acc[2 * p], ah, bl[0], bl[2]);
                mma16816(acc[2 * p], al, bh[0], bh[2]);
                mma16816(acc[2 * p + 1], ah, bh[1], bh[3]);
                mma16816(acc[2 * p + 1], ah, bl[1], bl[3]);
                mma16816(acc[2 * p + 1], al, bh[1], bh[3]);
            }
        }
    }
    const int rr = wid * 16 + (lane >> 2), cc = 2 * (lane & 3);
    float* outb = g_xg + (size_t)t * BB * 3072 + n0;
#pragma unroll
    for (int p = 0; p < 16; p++) {
        int col = p * 8 + cc;
        float2 v0 = {acc[p][0] + sb[col], acc[p][1] + sb[col + 1]};
        float2 v1 = {acc[p][2] + sb[col], acc[p][3] + sb[col + 1]};
        *(float2*)(outb + (size_t)rr * 3072 + col) = v0;
        *(float2*)(outb + (size_t)(rr + 8) * 3072 + col) = v1;
    }
}

// =====================================================================
// k_scan: persistent GRU scan, warp-private A staging (no block syncs
// inside k-loop). 128 blocks x 256 thr; block owns 8 units (24 cols).
// =====================================================================
#define SC_NB 128
#define SC_WP 1032
#define AW_P 72
// per-warp region: 2 bufs x (hi 16x72 + lo 16x72) = 4608 bf16
#define SCAN_SMEM ((2 * 24 * SC_WP + 8 * 4608) * 2)
__global__ void __launch_bounds__(256, 1) k_scan(const float* __restrict__ br) {
    extern __shared__ __nv_bfloat16 ssm[];
    __nv_bfloat16* Whi = ssm;
    __nv_bfloat16* Wlo = Whi + 24 * SC_WP;
    __nv_bfloat16* AB = Wlo + 24 * SC_WP;
    const int tid = threadIdx.x, wid = tid >> 5, lane = tid & 31;
    const int bid = blockIdx.x, u0 = bid * 8;

    for (int i = tid; i < 24 * 128; i += 256) {
        int n = i >> 7, j = (i & 127) * 8;
        *(uint4*)(Whi + n * SC_WP + j) = *(const uint4*)(g_rkhi + ((size_t)(bid * 24 + n)) * HH + j);
        *(uint4*)(Wlo + n * SC_WP + j) = *(const uint4*)(g_rklo + ((size_t)(bid * 24 + n)) * HH + j);
    }
    for (int i = tid; i < 128; i += 256) {
        uint4 z = {0, 0, 0, 0};
        *(uint4*)(g_hshi + (size_t)bid * HH + i * 8) = z;
        *(uint4*)(g_hslo + (size_t)bid * HH + i * 8) = z;
    }
    const int cc = 2 * (lane & 3);
    const float bz0 = br[u0 + cc], bz1 = br[u0 + cc + 1];
    const float brr0 = br[HH + u0 + cc], brr1 = br[HH + u0 + cc + 1];
    const float bh0 = br[2 * HH + u0 + cc], bh1 = br[2 * HH + u0 + cc + 1];
    float hp[4] = {0.f, 0.f, 0.f, 0.f};
    const int r1 = wid * 16 + (lane >> 2);
    const int b15 = lane & 15, bh8 = lane >> 4;
    const int b7 = lane & 7, bq = (lane >> 3) & 1;
    // warp-private staging mapping: 2 lanes per row, 4 uint4 each
    const int srow = lane >> 1, spart = (lane & 1) * 32;
    __nv_bfloat16* AW = AB + wid * 4608;
    const uint32_t aAddrBase = smem_u32(AW + (lane & 15) * AW_P + (lane >> 4) * 8);
    grid_barrier(SC_NB);

    for (int t = 0; t < TT; t++) {
        const float* xb = g_xg + (size_t)t * BB * 3072;
        float2 xz1 = *(const float2*)(xb + (size_t)r1 * 3072 + u0 + cc);
        float2 xr1 = *(const float2*)(xb + (size_t)r1 * 3072 + HH + u0 + cc);
        float2 xh1 = *(const float2*)(xb + (size_t)r1 * 3072 + 2 * HH + u0 + cc);
        float2 xz2 = *(const float2*)(xb + (size_t)(r1 + 8) * 3072 + u0 + cc);
        float2 xr2 = *(const float2*)(xb + (size_t)(r1 + 8) * 3072 + HH + u0 + cc);
        float2 xh2 = *(const float2*)(xb + (size_t)(r1 + 8) * 3072 + 2 * HH + u0 + cc);

        const __nv_bfloat16* Hhi = g_hshi + (size_t)t * BB * HH +
                                   (size_t)(wid * 16 + srow) * HH + spart;
        const __nv_bfloat16* Hlo = g_hslo + (size_t)t * BB * HH +
                                   (size_t)(wid * 16 + srow) * HH + spart;
        float acc[3][4];
#pragma unroll
        for (int i = 0; i < 3; i++)
#pragma unroll
            for (int j = 0; j < 4; j++) acc[i][j] = 0.f;

        uint4 ph[4], pl[4];
#pragma unroll
        for (int j = 0; j < 4; j++) {
            ph[j] = *(const uint4*)(Hhi + j * 8);
            pl[j] = *(const uint4*)(Hlo + j * 8);
        }
        {
            __nv_bfloat16* d = AW + srow * AW_P + spart;
#pragma unroll
            for (int j = 0; j < 4; j++) {
                *(uint4*)(d + j * 8) = ph[j];
                *(uint4*)(d + 1152 + j * 8) = pl[j];
            }
        }
        __syncwarp();

        for (int c = 0; c < 16; c++) {
            if (c < 15) {
#pragma unroll
                for (int j = 0; j < 4; j++) {
                    ph[j] = *(const uint4*)(Hhi + (c + 1) * 64 + j * 8);
                    pl[j] = *(const uint4*)(Hlo + (c + 1) * 64 + j * 8);
                }
            }
            const uint32_t aHi = aAddrBase + (uint32_t)((c & 1) * 2304 * 2);
            const uint32_t aLo = aHi + 1152 * 2;
#pragma unroll
            for (int kk = 0; kk < 4; kk++) {
                uint32_t ah[4], al[4];
                ldsm4(ah, aHi + kk * 32);
                ldsm4(al, aLo + kk * 32);
                const int kcol = c * 64 + kk * 16;
                uint32_t wh[4], wl[4], w2h[2], w2l[2];
                ldsm4(wh, smem_u32(Whi + b15 * SC_WP + kcol + bh8 * 8));
                ldsm4(wl, smem_u32(Wlo + b15 * SC_WP + kcol + bh8 * 8));
                ldsm2(w2h, smem_u32(Whi + (16 + b7) * SC_WP + kcol + bq * 8));
                ldsm2(w2l, smem_u32(Wlo + (16 + b7) * SC_WP + kcol + bq * 8));
                mma16816(acc[0], ah, wh[0], wh[2]);
                mma16816(acc[0], ah, wl[0], wl[2]);
                mma16816(acc[0], al, wh[0], wh[2]);
                mma16816(acc[1], ah, wh[1], wh[3]);
                mma16816(acc[1], ah, wl[1], wl[3]);
                mma16816(acc[1], al, wh[1], wh[3]);
                mma16816(acc[2], ah, w2h[0], w2h[1]);
                mma16816(acc[2], ah, w2l[0], w2l[1]);
                mma16816(acc[2], al, w2h[0], w2h[1]);
            }
            if (c < 15) {
                __nv_bfloat16* d = AW + ((c + 1) & 1) * 2304 + srow * AW_P + spart;
#pragma unroll
                for (int j = 0; j < 4; j++) {
                    *(uint4*)(d + j * 8) = ph[j];
                    *(uint4*)(d + 1152 + j * 8) = pl[j];
                }
            }
            __syncwarp();
        }
        // gates + state update (rows r1, r1+8; units u0+cc, +1)
        {
            float z, r, hh;
            z = sigm(xz1.x + acc[0][0] + bz0);
            r = sigm(xr1.x + acc[1][0] + brr0);
            hh = tanhf(xh1.x + r * (acc[2][0] + bh0));
            hp[0] = z * hp[0] + (1.f - z) * hh;
            z = sigm(xz1.y + acc[0][1] + bz1);
            r = sigm(xr1.y + acc[1][1] + brr1);
            hh = tanhf(xh1.y + r * (acc[2][1] + bh1));
            hp[1] = z * hp[1] + (1.f - z) * hh;
            z = sigm(xz2.x + acc[0][2] + bz0);
            r = sigm(xr2.x + acc[1][2] + brr0);
            hh = tanhf(xh2.x + r * (acc[2][2] + bh0));
            hp[2] = z * hp[2] + (1.f - z) * hh;
            z = sigm(xz2.y + acc[0][3] + bz1);
            r = sigm(xr2.y + acc[1][3] + brr1);
            hh = tanhf(xh2.y + r * (acc[2][3] + bh1));
            hp[3] = z * hp[3] + (1.f - z) * hh;

            __nv_bfloat16 h0, l0, h1, l1;
            bsplit(hp[0], h0, l0); bsplit(hp[1], h1, l1);
            size_t o1 = ((size_t)(t + 1) * BB + r1) * HH + u0 + cc;
            *(__nv_bfloat162*)(g_hshi + o1) = __nv_bfloat162(h0, h1);
            *(__nv_bfloat162*)(g_hslo + o1) = __nv_bfloat162(l0, l1);
            bsplit(hp[2], h0, l0); bsplit(hp[3], h1, l1);
            size_t o2 = ((size_t)(t + 1) * BB + r1 + 8) * HH + u0 + cc;
            *(__nv_bfloat162*)(g_hshi + o2) = __nv_bfloat162(h0, h1);
            *(__nv_bfloat162*)(g_hslo + o2) = __nv_bfloat162(l0, l1);
        }
        __threadfence();
        grid_barrier(SC_NB);
    }
}

// =====================================================================
// k_mlp: d = relu(hs @ w1 + b1), split output. grid 128 (=t), 256 thr
// =====================================================================
#define MB_P 136
#define MLP_SMEM (4 * 128 * MB_P * 2)
__global__ void __launch_bounds__(256, 1) k_mlp(const float* __restrict__ b1) {
    extern __shared__ __nv_bfloat16 msm[];
    __nv_bfloat16* Ahi = msm;
    __nv_bfloat16* Alo = Ahi + 128 * MB_P;
    __nv_bfloat16* Bhi = Alo + 128 * MB_P;
    __nv_bfloat16* Blo = Bhi + 128 * MB_P;
    __shared__ float sb[128];
    const int tid = threadIdx.x, wid = tid >> 5, lane = tid & 31;
    const int t = blockIdx.x;
    if (tid < 128) sb[tid] = b1[tid];
    float acc[16][4];
#pragma unroll
    for (int i = 0; i < 16; i++)
#pragma unroll
        for (int j = 0; j < 4; j++) acc[i][j] = 0.f;
    const int arow = wid * 16 + (lane & 15), ahalf = lane >> 4;
    const int br15 = lane & 15, bh8 = lane >> 4;
    const int lr = tid >> 1, lp = tid & 1;

    for (int kc = 0; kc < 8; kc++) {
        __syncthreads();
        {
            const __nv_bfloat16* sh = g_hshi + ((size_t)(t + 1) * BB + lr) * HH + kc * 128 + lp * 64;
            const __nv_bfloat16* sl = g_hslo + ((size_t)(t + 1) * BB + lr) * HH + kc * 128 + lp * 64;
            const __nv_bfloat16* wh = g_w1hi + (size_t)lr * HH + kc * 128 + lp * 64;
            const __nv_bfloat16* wl = g_w1lo + (size_t)lr * HH + kc * 128 + lp * 64;
#pragma unroll
            for (int j = 0; j < 64; j += 8) {
                *(uint4*)(Ahi + lr * MB_P + lp * 64 + j) = *(const uint4*)(sh + j);
                *(uint4*)(Alo + lr * MB_P + lp * 64 + j) = *(const uint4*)(sl + j);
                *(uint4*)(Bhi + lr * MB_P + lp * 64 + j) = *(const uint4*)(wh + j);
                *(uint4*)(Blo + lr * MB_P + lp * 64 + j) = *(const uint4*)(wl + j);
            }
        }
        __syncthreads();
#pragma unroll
        for (int kk = 0; kk < 8; kk++) {
            uint32_t ah[4], al[4];
            ldsm4(ah, smem_u32(Ahi + arow * MB_P + ahalf * 8 + kk * 16));
            ldsm4(al, smem_u32(Alo + arow * MB_P + ahalf * 8 + kk * 16));
#pragma unroll
            for (int p = 0; p < 8; p++) {
                uint32_t bh[4], bl[4];
                ldsm4(bh, smem_u32(Bhi + (p * 16 + br15) * MB_P + kk * 16 + bh8 * 8));
                ldsm4(bl, smem_u32(Blo + (p * 16 + br15) * MB_P + kk * 16 + bh8 * 8));
                mma16816(acc[2 * p], ah, bh[0], bh[2]);
                mma16816(acc[2 * p], ah, bl[0], bl[2]);
                mma16816(acc[2 * p], al, bh[0], bh[2]);
                mma16816(acc[2 * p + 1], ah, bh[1], bh[3]);
                mma16816(acc[2 * p + 1], ah, bl[1], bl[3]);
                mma16816(acc[2 * p + 1], al, bh[1], bh[3]);
            }
        }
    }
    const int rr = wid * 16 + (lane >> 2), cc = 2 * (lane & 3);
    const int m1 = t * BB + rr, m2 = m1 + 8;
#pragma unroll
    for (int p = 0; p < 16; p++) {
        int col = p * 8 + cc;
        float d0 = fmaxf(acc[p][0] + sb[col], 0.f);
        float d1 = fmaxf(acc[p][1] + sb[col + 1], 0.f);
        float d2 = fmaxf(acc[p][2] + sb[col], 0.f);
        float d3 = fmaxf(acc[p][3] + sb[col + 1], 0.f);
        __nv_bfloat16 h0, l0, h1, l1;
        bsplit(d0, h0, l0); bsplit(d1, h1, l1);
        *(__nv_bfloat162*)(g_dhi + (size_t)m1 * DD + col) = __nv_bfloat162(h0, h1);
        *(__nv_bfloat162*)(g_dlo + (size_t)m1 * DD + col) = __nv_bfloat162(l0, l1);
        bsplit(d2, h0, l0); bsplit(d3, h1, l1);
        *(__nv_bfloat162*)(g_dhi + (size_t)m2 * DD + col) = __nv_bfloat162(h0, h1);
        *(__nv_bfloat162*)(g_dlo + (size_t)m2 * DD + col) = __nv_bfloat162(l0, l1);
    }
}

// =====================================================================
// k_logits: logits = d @ w2 + b2. grid (79 n, 128 m), 256 thr.
// B in smem; A fragments direct LDG (occ 2).
// =====================================================================
#define LG_SMEM (2 * 128 * BP * 2)
__global__ void __launch_bounds__(256, 2) k_logits(const float* __restrict__ b2) {
    extern __shared__ __nv_bfloat16 lsm[];
    __nv_bfloat16* Bhi = lsm;
    __nv_bfloat16* Blo = Bhi + 128 * BP;
    __shared__ float sb[128];
    const int tid = threadIdx.x, wid = tid >> 5, lane = tid & 31;
    const int m0 = blockIdx.y * 128, n0 = blockIdx.x * 128;
    if (tid < 128) sb[tid] = (n0 + tid < VV) ? b2[n0 + tid] : 0.f;
    {
        const int lr = tid >> 1, lp = tid & 1;
        const __nv_bfloat16* wh = g_w2hi + (size_t)(n0 + lr) * DD + lp * 64;
        const __nv_bfloat16* wl = g_w2lo + (size_t)(n0 + lr) * DD + lp * 64;
#pragma unroll
        for (int j = 0; j < 64; j += 8) {
            *(uint4*)(Bhi + lr * BP + lp * 64 + j) = *(const uint4*)(wh + j);
            *(uint4*)(Blo + lr * BP + lp * 64 + j) = *(const uint4*)(wl + j);
        }
    }
    __syncthreads();
    float acc[16][4];
#pragma unroll
    for (int i = 0; i < 16; i++)
#pragma unroll
        for (int j = 0; j < 4; j++) acc[i][j] = 0.f;
    const int r0 = wid * 16 + (lane >> 2);
    const int kq = (lane & 3) * 2;
    const __nv_bfloat16* dh0 = g_dhi + (size_t)(m0 + r0) * DD;
    const __nv_bfloat16* dh1 = g_dhi + (size_t)(m0 + r0 + 8) * DD;
    const __nv_bfloat16* dl0 = g_dlo + (size_t)(m0 + r0) * DD;
    const __nv_bfloat16* dl1 = g_dlo + (size_t)(m0 + r0 + 8) * DD;
    const int br15 = lane & 15, bh8 = lane >> 4;
#pragma unroll
    for (int kt = 0; kt < 8; kt++) {
        const int k0 = kt * 16 + kq;
        uint32_t ah[4], al[4];
        ah[0] = *(const uint32_t*)(dh0 + k0);
        ah[1] = *(const uint32_t*)(dh1 + k0);
        ah[2] = *(const uint32_t*)(dh0 + k0 + 8);
        ah[3] = *(const uint32_t*)(dh1 + k0 + 8);
        al[0] = *(const uint32_t*)(dl0 + k0);
        al[1] = *(const uint32_t*)(dl1 + k0);
        al[2] = *(const uint32_t*)(dl0 + k0 + 8);
        al[3] = *(const uint32_t*)(dl1 + k0 + 8);
#pragma unroll
        for (int p = 0; p < 8; p++) {
            uint32_t bh[4], bl[4];
            ldsm4(bh, smem_u32(Bhi + (p * 16 + br15) * BP + kt * 16 + bh8 * 8));
            ldsm4(bl, smem_u32(Blo + (p * 16 + br15) * BP + kt * 16 + bh8 * 8));
            mma16816(acc[2 * p], ah, bh[0], bh[2]);
            mma16816(acc[2 * p], ah, bl[0], bl[2]);
            mma16816(acc[2 * p], al, bh[0], bh[2]);
            mma16816(acc[2 * p + 1], ah, bh[1], bh[3]);
            mma16816(acc[2 * p + 1], ah, bl[1], bl[3]);
            mma16816(acc[2 * p + 1], al, bh[1], bh[3]);
        }
    }
    const int rr = wid * 16 + (lane >> 2), cc = 2 * (lane & 3);
    float* o1 = g_logits + (size_t)(m0 + rr) * VV;
    float* o2 = g_logits + (size_t)(m0 + rr + 8) * VV;
#pragma unroll
    for (int p = 0; p < 16; p++) {
        int col = n0 + p * 8 + cc;
        if (col < VV) {
            float2 v0 = {acc[p][0] + sb[p * 8 + cc], acc[p][1] + sb[p * 8 + cc + 1]};
            float2 v1 = {acc[p][2] + sb[p * 8 + cc], acc[p][3] + sb[p * 8 + cc + 1]};
            *(float2*)(o1 + col) = v0;
            *(float2*)(o2 + col) = v1;
        }
    }
}

// =====================================================================
// k_softmax: online max+sum pass, then normalize-write. TEMP=0.02
// =====================================================================
__global__ __launch_bounds__(256) void k_softmax(float* __restrict__ out) {
    const int m = blockIdx.x;
    const int b = m & 127, t = m >> 7;
    const float* lr = g_logits + (size_t)m * VV;
    float* orow = out + ((size_t)b * TT + t) * VV;
    __shared__ float rm[8], rs[8];
    const int tid = threadIdx.x, lane = tid & 31, wid = tid >> 5;
    float mx = -1e30f, s = 0.f;
    for (int v = tid; v < VV; v += 256) {
        float x = lr[v] * 50.f;
        float nm = fmaxf(mx, x);
        s = s * __expf(mx - nm) + __expf(x - nm);
        mx = nm;
    }
#pragma unroll
    for (int o = 16; o; o >>= 1) {
        float om = __shfl_xor_sync(~0u, mx, o);
        float os = __shfl_xor_sync(~0u, s, o);
        float nm = fmaxf(mx, om);
        s = s * __expf(mx - nm) + os * __expf(om - nm);
        mx = nm;
    }
    if (lane == 0) { rm[wid] = mx; rs[wid] = s; }
    __syncthreads();
    if (tid == 0) {
        float M = rm[0], S = rs[0];
#pragma unroll
        for (int i = 1; i < 8; i++) {
            float nm = fmaxf(M, rm[i]);
            S = S * __expf(M - nm) + rs[i] * __expf(rm[i] - nm);
            M = nm;
        }
        rm[0] = M; rs[0] = 1.f / S;
    }
    __syncthreads();
    mx = rm[0];
    float inv = rs[0];
    for (int v = tid; v < VV; v += 256)
        orow[v] = __expf(lr[v] * 50.f - mx) * inv;
}

// =====================================================================
extern "C" void kernel_launch(void* const* d_in, const int* in_sizes, int n_in,
                              void* d_out, int out_size) {
    const int* tokens   = (const int*)d_in[0];
    const float* emb    = (const float*)d_in[1];
    const float* gru_k  = (const float*)d_in[2];
    const float* gru_rk = (const float*)d_in[3];
    const float* gru_bi = (const float*)d_in[4];
    const float* gru_br = (const float*)d_in[5];
    const float* w1     = (const float*)d_in[6];
    const float* b1     = (const float*)d_in[7];
    const float* w2     = (const float*)d_in[8];
    const float* b2     = (const float*)d_in[9];
    float* out = (float*)d_out;

    cudaFuncSetAttribute(k_xg, cudaFuncAttributeMaxDynamicSharedMemorySize, XG_SMEM);
    cudaFuncSetAttribute(k_scan, cudaFuncAttributeMaxDynamicSharedMemorySize, SCAN_SMEM);
    cudaFuncSetAttribute(k_mlp, cudaFuncAttributeMaxDynamicSharedMemorySize, MLP_SMEM);
    cudaFuncSetAttribute(k_logits, cudaFuncAttributeMaxDynamicSharedMemorySize, LG_SMEM);

    k_split<<<2048, 256>>>(emb, gru_k, gru_rk, w1, w2);
    k_xg<<<dim3(24, 128), 256, XG_SMEM>>>(tokens, gru_bi);
    k_scan<<<SC_NB, 256, SCAN_SMEM>>>(gru_br);
    k_mlp<<<128, 256, MLP_SMEM>>>(b1);
    k_logits<<<dim3(79, 128), 256, LG_SMEM>>>(b2);
    k_softmax<<<TT * BB, 256>>>(out);
}